// round 17
// baseline (speedup 1.0000x reference)
#include <cuda_runtime.h>

// DAVIS346 voxelization constants
#define CW 346
#define CH 260
#define CC 16
#define NUM_VOX (2 * CC * CH * CW)   // 2,877,440 floats
#define EV_PER_THREAD 2
#define TPB 64

__global__ __launch_bounds__(TPB)
void vox_scatter_kernel(const float4* __restrict__ ev,
                        float* __restrict__ out, int n) {
    int base = blockIdx.x * (TPB * EV_PER_THREAD) + threadIdx.x;

    // Two independent streaming loads (MLP=2) — measured optimum across the
    // EV={1,2,4,8} sweep (covers latency without flooding the L1tex queue).
    float4 e0 = (base < n)       ? __ldcs(&ev[base])       : make_float4(0.f, 0.f, -1.f, 0.f);
    float4 e1 = (base + TPB < n) ? __ldcs(&ev[base + TPB]) : make_float4(0.f, 0.f, -1.f, 0.f);

    // idx = x + 346*y + 346*260*((ceil(16t)-1) + 16*(p>0)); exact in fp32 (<2^24)
    float fb0 = ceilf(e0.z * (float)CC) - 1.0f + ((e0.w > 0.0f) ? (float)CC : 0.0f);
    float fb1 = ceilf(e1.z * (float)CC) - 1.0f + ((e1.w > 0.0f) ? (float)CC : 0.0f);
    int idx0 = (int)fmaf((float)(CW * CH), fb0, fmaf((float)CW, e0.y, e0.x));
    int idx1 = (int)fmaf((float)(CW * CH), fb1, fmaf((float)CW, e1.y, e1.x));
    bool v0 = (e0.z > 0.0f) && (e0.z <= 1.0f);
    bool v1 = (e1.z > 0.0f) && (e1.z <= 1.0f);

    // PDL: event loads above may overlap the memset; stores wait for it.
    cudaGridDependencySynchronize();

    if (v0) out[idx0] = 1.0f;   // non-accumulating scatter, races benign
    if (v1) out[idx1] = 1.0f;
}

extern "C" void kernel_launch(void* const* d_in, const int* in_sizes, int n_in,
                              void* d_out, int out_size) {
    const float4* ev = (const float4*)d_in[0];
    float* out = (float*)d_out;
    int n = in_sizes[0] / 4;              // events are [N,4] float32

    // 1) zero the output (harness poisons d_out) — async memset, capturable.
    //    Measured cheaper than zero-kernel and all in-kernel zeroing schemes.
    cudaMemsetAsync(out, 0, (size_t)NUM_VOX * sizeof(float), 0);

    // 2) scatter with programmatic dependent launch.
    int blocks = (n + TPB * EV_PER_THREAD - 1) / (TPB * EV_PER_THREAD);
    cudaLaunchConfig_t cfg = {};
    cfg.gridDim  = dim3(blocks, 1, 1);
    cfg.blockDim = dim3(TPB, 1, 1);
    cfg.dynamicSmemBytes = 0;
    cfg.stream = 0;
    cudaLaunchAttribute attr[1];
    attr[0].id = cudaLaunchAttributeProgrammaticStreamSerialization;
    attr[0].val.programmaticStreamSerializationAllowed = 1;
    cfg.attrs = attr;
    cfg.numAttrs = 1;
    cudaLaunchKernelEx(&cfg, vox_scatter_kernel, ev, out, n);
}